// round 14
// baseline (speedup 1.0000x reference)
#include <cuda_runtime.h>
#include <cuda_fp16.h>
#include <cstdint>
#include <math.h>

// Problem constants
#define BATCH 2
#define SEQ   2048
#define HID   2048
#define NHEAD 16
#define HDIM  128
#define TOK   (BATCH * SEQ)      // 4096 rows
#define FF    (4 * HID)          // 8192

// ---------------- scratch (device globals; no allocation) ----------------
__device__ __align__(256) __half g_h   [TOK * HID];       // LN out (fp16)
__device__ __align__(256) __half g_qkv [TOK * 3 * HID];   // QKV (fp16)
__device__ __align__(256) __half g_attn[TOK * HID];       // attn out (fp16)
__device__ float                 g_x1  [TOK * HID];       // residual-1 (fp32)
__device__ __align__(256) __half g_ff  [TOK * FF];        // gelu(ff1) (fp16)
// transposed weights [N, K] fp16
__device__ __align__(256) __half g_wt_qkv[3 * HID * HID];
__device__ __align__(256) __half g_wt_ao [HID * HID];
__device__ __align__(256) __half g_wt_ff1[FF * HID];
__device__ __align__(256) __half g_wt_ff2[HID * FF];

// ---------------- helpers ----------------
__device__ __forceinline__ uint32_t smem_u32(const void* p) {
    uint32_t a;
    asm("{ .reg .u64 t; cvta.to.shared.u64 t, %1; cvt.u32.u64 %0, t; }"
        : "=r"(a) : "l"(p));
    return a;
}
#define SW128(o) ((o) ^ (((o) >> 3) & 0x70))

__device__ __forceinline__ uint32_t h2_to_u32(__half2 h) {
    return *reinterpret_cast<uint32_t*>(&h);
}

__device__ __forceinline__ void cp16(uint32_t dst, const void* src) {
    asm volatile("cp.async.cg.shared.global [%0], [%1], 16;"
                 :: "r"(dst), "l"(src) : "memory");
}

#define LDSM4(r0, r1, r2, r3, addr) \
    asm volatile("ldmatrix.sync.aligned.m8n8.x4.shared.b16 {%0,%1,%2,%3}, [%4];" \
                 : "=r"(r0), "=r"(r1), "=r"(r2), "=r"(r3) : "r"(addr))

#define LDSM4T(r0, r1, r2, r3, addr) \
    asm volatile("ldmatrix.sync.aligned.m8n8.x4.trans.shared.b16 {%0,%1,%2,%3}, [%4];" \
                 : "=r"(r0), "=r"(r1), "=r"(r2), "=r"(r3) : "r"(addr))

__device__ __forceinline__ void hmma(float* c,
    uint32_t a0, uint32_t a1, uint32_t a2, uint32_t a3, uint32_t b0, uint32_t b1)
{
    asm volatile(
        "mma.sync.aligned.m16n8k16.row.col.f32.f16.f16.f32 "
        "{%0,%1,%2,%3}, {%4,%5,%6,%7}, {%8,%9}, {%0,%1,%2,%3};"
        : "+f"(c[0]), "+f"(c[1]), "+f"(c[2]), "+f"(c[3])
        : "r"(a0), "r"(a1), "r"(a2), "r"(a3), "r"(b0), "r"(b1));
}

__device__ __forceinline__ float gelu_f(float x) {
    float x3 = x * x * x;
    float t = tanhf(0.7978845608028654f * (x + 0.044715f * x3));
    return 0.5f * x * (1.0f + t);
}

// ---------------- fp16 tensor-core GEMM (R7 shape + reg double-buffer) ----------------
#define BM 128
#define BN 128
#define BKH 64
#define NST 3
#define STAGE_A_BYTES (BM * BKH * 2)
#define STAGE_B_BYTES (BN * BKH * 2)
#define STG_BYTES (STAGE_A_BYTES + STAGE_B_BYTES)
#define HGEMM_SMEM (STG_BYTES * NST)

#define EPI_BIAS       0
#define EPI_BIAS_GELU  1
#define EPI_BIAS_RESID 2

__device__ __forceinline__ void hload_chunk(
    uint32_t sA, uint32_t sB, const __half* __restrict__ A,
    const __half* __restrict__ BT, int m0, int n0, int k0, int K, int tid)
{
    #pragma unroll
    for (int i = 0; i < 4; i++) {
        int f = tid + 256 * i;
        int r = f >> 3, c = f & 7;
        cp16(sA + SW128(r * 128 + c * 16), A + (size_t)(m0 + r) * K + k0 + c * 8);
    }
    #pragma unroll
    for (int i = 0; i < 4; i++) {
        int f = tid + 256 * i;
        int r = f >> 3, c = f & 7;
        cp16(sB + SW128(r * 128 + c * 16), BT + (size_t)(n0 + r) * K + k0 + c * 8);
    }
    asm volatile("cp.async.commit_group;" ::: "memory");
}

template <typename OutT>
__device__ __forceinline__ void store_pair(OutT* p, float v0, float v1);
template <>
__device__ __forceinline__ void store_pair<float>(float* p, float v0, float v1) {
    *(float2*)p = make_float2(v0, v1);
}
template <>
__device__ __forceinline__ void store_pair<__half>(__half* p, float v0, float v1) {
    *(__half2*)p = __floats2half2_rn(v0, v1);
}

template <int EPI, typename OutT>
__global__ __launch_bounds__(256, 2) void hgemm(
    const __half* __restrict__ A, const __half* __restrict__ BT,
    const float* __restrict__ bias, const float* __restrict__ resid,
    OutT* __restrict__ C, int M, int N, int K)
{
    extern __shared__ char sm_raw[];
    const uint32_t sbase = smem_u32(sm_raw);

    const int tid = threadIdx.x;
    const int lane = tid & 31, wid = tid >> 5;
    const int wm = (wid >> 2) * 64;
    const int wn = (wid & 3) * 32;
    const int m0 = blockIdx.y * BM, n0 = blockIdx.x * BN;

    const int a_hi = lane >> 4;
    const int b_hi = (lane >> 3) & 1;
    int arow[4], brow[2];
    #pragma unroll
    for (int mt = 0; mt < 4; mt++) arow[mt] = wm + mt * 16 + (lane & 15);
    #pragma unroll
    for (int p = 0; p < 2; p++)
        brow[p] = wn + p * 16 + ((lane >> 4) << 3) + (lane & 7);

    float acc[4][4][4];
    #pragma unroll
    for (int mt = 0; mt < 4; mt++)
        #pragma unroll
        for (int nt = 0; nt < 4; nt++)
            #pragma unroll
            for (int i = 0; i < 4; i++) acc[mt][nt][i] = 0.f;

    const int nc = K / BKH;

    hload_chunk(sbase, sbase + STAGE_A_BYTES, A, BT, m0, n0, 0, K, tid);
    hload_chunk(sbase + STG_BYTES, sbase + STG_BYTES + STAGE_A_BYTES,
                A, BT, m0, n0, BKH, K, tid);

    uint32_t af[2][4][4];
    uint32_t bf[2][4][2];

    for (int k = 0; k < nc; k++) {
        const uint32_t sA = sbase + (k % NST) * STG_BYTES;
        const uint32_t sB = sA + STAGE_A_BYTES;

        asm volatile("cp.async.wait_group 1;" ::: "memory");
        __syncthreads();

        if (k + 2 < nc) {
            const uint32_t pA = sbase + ((k + 2) % NST) * STG_BYTES;
            hload_chunk(pA, pA + STAGE_A_BYTES, A, BT, m0, n0, (k + 2) * BKH, K, tid);
        } else {
            asm volatile("cp.async.commit_group;" ::: "memory");
        }

        // load fragments for kk=0 into buffer 0
        #pragma unroll
        for (int mt = 0; mt < 4; mt++) {
            const int row = arow[mt];
            LDSM4(af[0][mt][0], af[0][mt][1], af[0][mt][2], af[0][mt][3],
                  sA + row * 128 + ((a_hi ^ (row & 7)) << 4));
        }
        #pragma unroll
        for (int p = 0; p < 2; p++) {
            const int row = brow[p];
            uint32_t r0, r1, r2, r3;
            LDSM4(r0, r1, r2, r3, sB + row * 128 + ((b_hi ^ (row & 7)) << 4));
            bf[0][2 * p][0] = r0; bf[0][2 * p][1] = r1;
            bf[0][2 * p + 1][0] = r2; bf[0][2 * p + 1][1] = r3;
        }

        #pragma unroll
        for (int kk = 0; kk < 4; kk++) {
            const int cur = kk & 1, nxt = cur ^ 1;
            if (kk < 3) {
                // prefetch fragments for kk+1 while computing kk
                #pragma unroll
                for (int mt = 0; mt < 4; mt++) {
                    const int row = arow[mt];
                    LDSM4(af[nxt][mt][0], af[nxt][mt][1], af[nxt][mt][2], af[nxt][mt][3],
                          sA + row * 128 + (((((kk + 1) << 1) + a_hi) ^ (row & 7)) << 4));
                }
                #pragma unroll
                for (int p = 0; p < 2; p++) {
                    const int row = brow[p];
                    uint32_t r0, r1, r2, r3;
                    LDSM4(r0, r1, r2, r3,
                          sB + row * 128 + (((((kk + 1) << 1) + b_hi) ^ (row & 7)) << 4));
                    bf[nxt][2 * p][0] = r0; bf[nxt][2 * p][1] = r1;
                    bf[nxt][2 * p + 1][0] = r2; bf[nxt][2 * p + 1][1] = r3;
                }
            }
            #pragma unroll
            for (int mt = 0; mt < 4; mt++)
                #pragma unroll
                for (int nt = 0; nt < 4; nt++)
                    hmma(acc[mt][nt],
                         af[cur][mt][0], af[cur][mt][1], af[cur][mt][2], af[cur][mt][3],
                         bf[cur][nt][0], bf[cur][nt][1]);
        }
    }

    const int g = lane >> 2, q = lane & 3;
    #pragma unroll
    for (int mt = 0; mt < 4; mt++) {
        #pragma unroll
        for (int nt = 0; nt < 4; nt++) {
            const int col = n0 + wn + nt * 8 + 2 * q;
            const float2 bv = *(const float2*)(bias + col);
            #pragma unroll
            for (int hh = 0; hh < 2; hh++) {
                const int row = m0 + wm + mt * 16 + g + hh * 8;
                float v0 = acc[mt][nt][2 * hh]     + bv.x;
                float v1 = acc[mt][nt][2 * hh + 1] + bv.y;
                if (EPI == EPI_BIAS_GELU) { v0 = gelu_f(v0); v1 = gelu_f(v1); }
                if (EPI == EPI_BIAS_RESID) {
                    const float2 rv = *(const float2*)(resid + (size_t)row * N + col);
                    v0 += rv.x; v1 += rv.y;
                }
                store_pair<OutT>(C + (size_t)row * N + col, v0, v1);
            }
        }
    }
}

// ---------------- weight transpose: W[K,N] fp32 -> WT[N,K] fp16 ----------------
__global__ __launch_bounds__(256) void transpose_kernel(
    const float* __restrict__ W, __half* __restrict__ WT, int K, int N)
{
    __shared__ float t[32][33];
    const int nx = blockIdx.x * 32, kx = blockIdx.y * 32;
    const int tx = threadIdx.x, ty = threadIdx.y;
    #pragma unroll
    for (int i = 0; i < 32; i += 8)
        t[ty + i][tx] = W[(size_t)(kx + ty + i) * N + nx + tx];
    __syncthreads();
    #pragma unroll
    for (int i = 0; i < 32; i += 8)
        WT[(size_t)(nx + ty + i) * K + kx + tx] = __float2half_rn(t[tx][ty + i]);
}

// ---------------- LayerNorm (fp32 in, fp16 out) ----------------
__global__ __launch_bounds__(256) void ln_kernel(
    const float* __restrict__ x, const float* __restrict__ g,
    const float* __restrict__ b, __half* __restrict__ o)
{
    const int row = blockIdx.x;
    const float* xr = x + (size_t)row * HID;
    __half* orow = o + (size_t)row * HID;
    const int tid = threadIdx.x;

    float4 v0 = *(const float4*)(xr + tid * 4);
    float4 v1 = *(const float4*)(xr + 1024 + tid * 4);

    float s = v0.x + v0.y + v0.z + v0.w + v1.x + v1.y + v1.z + v1.w;
    float q = v0.x*v0.x + v0.y*v0.y + v0.z*v0.z + v0.w*v0.w
            + v1.x*v1.x + v1.y*v1.y + v1.z*v1.z + v1.w*v1.w;

    #pragma unroll
    for (int off = 16; off; off >>= 1) {
        s += __shfl_xor_sync(0xffffffffu, s, off);
        q += __shfl_xor_sync(0xffffffffu, q, off);
    }
    __shared__ float ss[8], sq[8];
    __shared__ float stats[2];
    const int wid = tid >> 5, lane = tid & 31;
    if (lane == 0) { ss[wid] = s; sq[wid] = q; }
    __syncthreads();
    if (tid == 0) {
        float S = 0.f, Q = 0.f;
        #pragma unroll
        for (int w = 0; w < 8; w++) { S += ss[w]; Q += sq[w]; }
        float mu = S * (1.0f / HID);
        float var = Q * (1.0f / HID) - mu * mu;
        stats[0] = mu;
        stats[1] = rsqrtf(var + 1e-5f);
    }
    __syncthreads();
    const float mu = stats[0], rs = stats[1];

    float4 g0 = *(const float4*)(g + tid * 4);
    float4 g1 = *(const float4*)(g + 1024 + tid * 4);
    float4 b0 = *(const float4*)(b + tid * 4);
    float4 b1 = *(const float4*)(b + 1024 + tid * 4);

    __half2 h0[2], h1[2];
    h0[0] = __floats2half2_rn((v0.x - mu) * rs * g0.x + b0.x,
                              (v0.y - mu) * rs * g0.y + b0.y);
    h0[1] = __floats2half2_rn((v0.z - mu) * rs * g0.z + b0.z,
                              (v0.w - mu) * rs * g0.w + b0.w);
    h1[0] = __floats2half2_rn((v1.x - mu) * rs * g1.x + b1.x,
                              (v1.y - mu) * rs * g1.y + b1.y);
    h1[1] = __floats2half2_rn((v1.z - mu) * rs * g1.z + b1.z,
                              (v1.w - mu) * rs * g1.w + b1.w);
    *(uint2*)(orow + tid * 4)        = *(uint2*)h0;
    *(uint2*)(orow + 1024 + tid * 4) = *(uint2*)h1;
}

// ---------------- fp16 tensor-core flash attention (causal) ----------------
#define AQ 128
#define AKV 64
#define ATT_Q_BYTES  (AQ * 256)
#define ATT_KV_BYTES (AKV * 256)
#define ATT_SMEM (ATT_Q_BYTES + 4 * ATT_KV_BYTES)

__device__ __forceinline__ uint32_t sw_row256(uint32_t base, int row, int u) {
    return base + row * 256 + ((u >> 3) << 7) + ((((u & 7) ^ (row & 7))) << 4);
}

__global__ __launch_bounds__(256) void attn_kernel(
    const __half* __restrict__ qkv, __half* __restrict__ out)
{
    extern __shared__ char asm_raw[];
    const uint32_t sbase = smem_u32(asm_raw);
    const uint32_t sQ = sbase;
    const uint32_t sK0 = sbase + ATT_Q_BYTES;
    const uint32_t sK1 = sK0 + ATT_KV_BYTES;
    const uint32_t sV0 = sK1 + ATT_KV_BYTES;
    const uint32_t sV1 = sV0 + ATT_KV_BYTES;

    const int qb = blockIdx.x, h = blockIdx.y, bb = blockIdx.z;
    const int tid = threadIdx.x;
    const int lane = tid & 31, wid = tid >> 5;
    const int q0 = qb * AQ;
    const float SC = 0.08838834764831845f;
    const size_t base = (size_t)bb * SEQ * (3 * HID) + (size_t)h * HDIM;

    #pragma unroll
    for (int i = 0; i < 8; i++) {
        int f = tid + 256 * i;
        int r = f >> 4, u = f & 15;
        cp16(sw_row256(sQ, r, u), qkv + base + (size_t)(q0 + r) * (3 * HID) + u * 8);
    }
    asm volatile("cp.async.commit_group;" ::: "memory");
    asm volatile("cp.async.wait_group 0;" ::: "memory");
    __syncthreads();

    const int nkb = qb * 2 + 2;

    {
        #pragma unroll
        for (int i = 0; i < 4; i++) {
            int f = tid + 256 * i;
            int r = f >> 4, u = f & 15;
            const __half* src = qkv + base + (size_t)r * (3 * HID) + u * 8;
            cp16(sw_row256(sK0, r, u), src + HID);
            cp16(sw_row256(sV0, r, u), src + 2 * HID);
        }
        asm volatile("cp.async.commit_group;" ::: "memory");
        #pragma unroll
        for (int i = 0; i < 4; i++) {
            int f = tid + 256 * i;
            int r = f >> 4, u = f & 15;
            const __half* src = qkv + base + (size_t)(AKV + r) * (3 * HID) + u * 8;
            cp16(sw_row256(sK1, r, u), src + HID);
            cp16(sw_row256(sV1, r, u), src + 2 * HID);
        }
        asm volatile("cp.async.commit_group;" ::: "memory");
    }

    const int g = lane >> 2, q2 = (lane & 3) * 2;
    const int wq = wid * 16;
    const int arow = wq + (lane & 15);
    const int a_hi = lane >> 4;
    const int b_hi = (lane >> 3) & 1;

    const int qrow0 = q0 + wq + g;
    const int qrow1 = qrow0 + 8;

    float m0 = -1e30f, m1 = -1e30f, l0 = 0.f, l1 = 0.f;
    float o[16][4];
    #pragma unroll
    for (int nt = 0; nt < 16; nt++)
        #pragma unroll
        for (int i = 0; i < 4; i++) o[nt][i] = 0.f;

    for (int kb = 0; kb < nkb; kb++) {
        const uint32_t sK = (kb & 1) ? sK1 : sK0;
        const uint32_t sV = (kb & 1) ? sV1 : sV0;

        asm volatile("cp.async.wait_group 1;" ::: "memory");
        __syncthreads();

        float sacc[8][4];
        #pragma unroll
        for (int nt = 0; nt < 8; nt++)
            #pragma unroll
            for (int i = 0; i < 4; i++) sacc[nt][i] = 0.f;

        #pragma unroll
        for (int kk = 0; kk < 8; kk++) {
            uint32_t a0, a1, a2, a3;
            LDSM4(a0, a1, a2, a3, sw_row256(sQ, arow, (kk << 1) + a_hi));
            #pragma unroll
            for (int p = 0; p < 2; p++) {
                const int row0 = p * 32 + ((lane >> 4) << 3) + (lane & 7);
                uint32_t r0, r1, r2, r3;
                LDSM4(r0, r1, r2, r3, sw_row256(sK, row0, (kk << 1) + b_hi));
                hmma(sacc[4 * p + 0], a0, a1, a2, a3, r0, r1);
                hmma(sacc[4 * p + 1], a0, a1, a2, a3, r2, r3);
                const int row1 = row0 + 16;
                LDSM4(r0, r1, r2, r3, sw_row256(sK, row1, (kk << 1) + b_hi));
                hmma(sacc[4 * p + 2], a0, a1, a2, a3, r0, r1);
                hmma(sacc[4 * p + 3], a0, a1, a2, a3, r2, r3);
            }
        }

        const bool need_mask = (kb * AKV + AKV - 1) > (q0 + wq);
        float mt0 = -1e30f, mt1 = -1e30f;
        #pragma unroll
        for (int nt = 0; nt < 8; nt++) {
            const int key = kb * AKV + nt * 8 + q2;
            float s0 = sacc[nt][0] * SC, s1 = sacc[nt][1] * SC;
            float s2 = sacc[nt][2] * SC, s3 = sacc[nt][3] * SC;
            if (need_mask) {
                if (key     > qrow0) s0 = -1e30f;
                if (key + 1 > qrow0) s1 = -1e30f;
                if (key     > qrow1) s2 = -1e30f;
                if (key + 1 > qrow1) s3 = -1e30f;
            }
            sacc[nt][0] = s0; sacc[nt][1] = s1;
            sacc[nt][2] = s2; sacc[nt][3] = s3;
            mt0 = fmaxf(mt0, fmaxf(s0, s1));
            mt1 = fmaxf(mt1, fmaxf(s2, s3));
        }
        mt0 = fmaxf(mt0, __shfl_xor_sync(0xffffffffu, mt0, 1));
        mt0 = fmaxf(mt0, __shfl_xor_sync(0xffffffffu, mt0, 2));
        mt1 = fmaxf(mt1, __shfl_xor_sync(0xffffffffu, mt1, 1));
        mt1 = fmaxf(mt1, __shfl_xor_sync(0xffffffffu, mt1, 2));

        const float mn0 = fmaxf(m0, mt0), mn1 = fmaxf(m1, mt1);
        const float fs0 = __expf(m0 - mn0), fs1 = __expf(m1 - mn1);
        m0 = mn0; m1 = mn1;

        uint32_t p01[8], p23[8];
        float rs0 = 0.f, rs1 = 0.f;
        #pragma unroll
        for (int nt = 0; nt < 8; nt++) {
            float e0 = __expf(sacc[nt][0] - mn0);
            float e1 = __expf(sacc[nt][1] - mn0);
            float e2 = __expf(sacc[nt][2] - mn1);
            float e3 = __expf(sacc[nt][3] - mn1);
            rs0 += e0 + e1; rs1 += e2 + e3;
            p01[nt] = h2_to_u32(__floats2half2_rn(e0, e1));
            p23[nt] = h2_to_u32(__floats2half2_rn(e2, e3));
        }
        rs0 += __shfl_xor_sync(0xffffffffu, rs0, 1);
        rs0 += __shfl_xor_sync(0xffffffffu, rs0, 2);
        rs1 += __shfl_xor_sync(0xffffffffu, rs1, 1);
        rs1 += __shfl_xor_sync(0xffffffffu, rs1, 2);
        l0 = l0 * fs0 + rs0;
        l1 = l1 * fs1 + rs1;

        #pragma unroll
        for (int nt = 0; nt < 16; nt++) {
            o[nt][0] *= fs0; o[nt][1] *= fs0;
            o[nt][2] *= fs1; o[nt][3] *= fs1;
        }

        #pragma unroll
        for (int kt = 0; kt < 4; kt++) {
            const uint32_t a0 = p01[2 * kt], a1 = p23[2 * kt];
            const uint32_t a2 = p01[2 * kt + 1], a3 = p23[2 * kt + 1];
            const int vkey = kt * 16 + (lane & 15);
            #pragma unroll
            for (int ndp = 0; ndp < 8; ndp++) {
                const int d = ndp * 16 + ((lane >> 4) << 3);
                uint32_t r0, r1, r2, r3;
                LDSM4T(r0, r1, r2, r3, sw_row256(sV, vkey, d >> 3));
                hmma(o[2 * ndp],     a0, a1, a2, a3, r0, r1);
                hmma(o[2 * ndp + 1], a0, a1, a2, a3, r2, r3);
            }
        }

        __syncthreads();

        if (kb + 2 < nkb) {
            const uint32_t pK = (kb & 1) ? sK1 : sK0;
            const uint32_t pV = (kb & 1) ? sV1 : sV0;
            const int k0n = (kb + 2) * AKV;
            #pragma unroll
            for (int i = 0; i < 4; i++) {
                int f = tid + 256 * i;
                int r = f >> 4, u = f & 15;
                const __half* src = qkv + base + (size_t)(k0n + r) * (3 * HID) + u * 8;
                cp16(sw_row256(pK, r, u), src + HID);
                cp16(sw_row256(pV, r, u), src + 2 * HID);
            }
        }
        asm volatile("cp.async.commit_group;" ::: "memory");
    }

    const float inv0 = 1.0f / l0, inv1 = 1.0f / l1;
    __half* ob = out + ((size_t)bb * SEQ) * HID + (size_t)h * HDIM;
    #pragma unroll
    for (int nt = 0; nt < 16; nt++) {
        const int col = nt * 8 + q2;
        *(__half2*)(ob + (size_t)(q0 + wq + g) * HID + col) =
            __floats2half2_rn(o[nt][0] * inv0, o[nt][1] * inv0);
        *(__half2*)(ob + (size_t)(q0 + wq + g + 8) * HID + col) =
            __floats2half2_rn(o[nt][2] * inv1, o[nt][3] * inv1);
    }
}

// ---------------- host ----------------
extern "C" void kernel_launch(void* const* d_in, const int* in_sizes, int n_in,
                              void* d_out, int out_size)
{
    const float* x     = (const float*)d_in[0];
    const float* ln1_g = (const float*)d_in[1];
    const float* ln1_b = (const float*)d_in[2];
    const float* ln2_g = (const float*)d_in[3];
    const float* ln2_b = (const float*)d_in[4];
    const float* w_qkv = (const float*)d_in[5];
    const float* b_qkv = (const float*)d_in[6];
    const float* w_ao  = (const float*)d_in[7];
    const float* b_ao  = (const float*)d_in[8];
    const float* w_ff1 = (const float*)d_in[9];
    const float* b_ff1 = (const float*)d_in[10];
    const float* w_ff2 = (const float*)d_in[11];
    const float* b_ff2 = (const float*)d_in[12];
    float* out = (float*)d_out;

    __half *h, *qkv, *attn, *ffb, *wt_qkv, *wt_ao, *wt_ff1, *wt_ff2;
    float *x1;
    cudaGetSymbolAddress((void**)&h,      g_h);
    cudaGetSymbolAddress((void**)&qkv,    g_qkv);
    cudaGetSymbolAddress((void**)&attn,   g_attn);
    cudaGetSymbolAddress((void**)&x1,     g_x1);
    cudaGetSymbolAddress((void**)&ffb,    g_ff);
    cudaGetSymbolAddress((void**)&wt_qkv, g_wt_qkv);
    cudaGetSymbolAddress((void**)&wt_ao,  g_wt_ao);
    cudaGetSymbolAddress((void**)&wt_ff1, g_wt_ff1);
    cudaGetSymbolAddress((void**)&wt_ff2, g_wt_ff2);

    cudaFuncSetAttribute(attn_kernel,
                         cudaFuncAttributeMaxDynamicSharedMemorySize, ATT_SMEM);
    cudaFuncSetAttribute(hgemm<EPI_BIAS, __half>,
                         cudaFuncAttributeMaxDynamicSharedMemorySize, HGEMM_SMEM);
    cudaFuncSetAttribute(hgemm<EPI_BIAS_GELU, __half>,
                         cudaFuncAttributeMaxDynamicSharedMemorySize, HGEMM_SMEM);
    cudaFuncSetAttribute(hgemm<EPI_BIAS_RESID, float>,
                         cudaFuncAttributeMaxDynamicSharedMemorySize, HGEMM_SMEM);

    // 0) transpose + convert weights to fp16 [N, K]
    transpose_kernel<<<dim3(3 * HID / 32, HID / 32), dim3(32, 8)>>>(w_qkv, wt_qkv, HID, 3 * HID);
    transpose_kernel<<<dim3(HID / 32, HID / 32),     dim3(32, 8)>>>(w_ao,  wt_ao,  HID, HID);
    transpose_kernel<<<dim3(FF / 32, HID / 32),      dim3(32, 8)>>>(w_ff1, wt_ff1, HID, FF);
    transpose_kernel<<<dim3(HID / 32, FF / 32),      dim3(32, 8)>>>(w_ff2, wt_ff2, FF, HID);

    // 1) LN1 -> fp16
    ln_kernel<<<TOK, 256>>>(x, ln1_g, ln1_b, h);
    // 2) QKV = h @ w_qkv + b_qkv  (fp16 out)
    hgemm<EPI_BIAS, __half><<<dim3(3 * HID / BN, TOK / BM), 256, HGEMM_SMEM>>>(
        h, wt_qkv, b_qkv, nullptr, qkv, TOK, 3 * HID, HID);
    // 3) attention (fp16 tensor cores, fp16 out)
    attn_kernel<<<dim3(SEQ / AQ, NHEAD, BATCH), 256, ATT_SMEM>>>(qkv, attn);
    // 4) x1 = x + attn @ w_ao + b_ao  (fp32 out)
    hgemm<EPI_BIAS_RESID, float><<<dim3(HID / BN, TOK / BM), 256, HGEMM_SMEM>>>(
        attn, wt_ao, b_ao, x, x1, TOK, HID, HID);
    // 5) LN2 -> fp16
    ln_kernel<<<TOK, 256>>>(x1, ln2_g, ln2_b, h);
    // 6) ff = gelu(h @ w_ff1 + b_ff1)  (fp16 out)
    hgemm<EPI_BIAS_GELU, __half><<<dim3(FF / BN, TOK / BM), 256, HGEMM_SMEM>>>(
        h, wt_ff1, b_ff1, nullptr, ffb, TOK, FF, HID);
    // 7) out = x1 + ff @ w_ff2 + b_ff2  (fp32 out)
    hgemm<EPI_BIAS_RESID, float><<<dim3(HID / BN, TOK / BM), 256, HGEMM_SMEM>>>(
        ffb, wt_ff2, b_ff2, x1, out, TOK, HID, FF);
}

// round 16
// speedup vs baseline: 1.5570x; 1.5570x over previous
#include <cuda_runtime.h>
#include <cuda_fp16.h>
#include <cstdint>
#include <math.h>

// Problem constants
#define BATCH 2
#define SEQ   2048
#define HID   2048
#define NHEAD 16
#define HDIM  128
#define TOK   (BATCH * SEQ)      // 4096 rows
#define FF    (4 * HID)          // 8192

// ---------------- scratch (device globals; no allocation) ----------------
__device__ __align__(256) __half g_h   [TOK * HID];       // LN out (fp16)
__device__ __align__(256) __half g_qkv [TOK * 3 * HID];   // QKV (fp16)
__device__ __align__(256) __half g_attn[TOK * HID];       // attn out (fp16)
__device__ float                 g_x1  [TOK * HID];       // residual-1 (fp32)
__device__ __align__(256) __half g_ff  [TOK * FF];        // gelu(ff1) (fp16)
// transposed weights [N, K] fp16
__device__ __align__(256) __half g_wt_qkv[3 * HID * HID];
__device__ __align__(256) __half g_wt_ao [HID * HID];
__device__ __align__(256) __half g_wt_ff1[FF * HID];
__device__ __align__(256) __half g_wt_ff2[HID * FF];

// ---------------- helpers ----------------
__device__ __forceinline__ uint32_t smem_u32(const void* p) {
    uint32_t a;
    asm("{ .reg .u64 t; cvta.to.shared.u64 t, %1; cvt.u32.u64 %0, t; }"
        : "=r"(a) : "l"(p));
    return a;
}
#define SW128(o) ((o) ^ (((o) >> 3) & 0x70))

__device__ __forceinline__ uint32_t h2_to_u32(__half2 h) {
    return *reinterpret_cast<uint32_t*>(&h);
}

__device__ __forceinline__ void cp16(uint32_t dst, const void* src) {
    asm volatile("cp.async.cg.shared.global [%0], [%1], 16;"
                 :: "r"(dst), "l"(src) : "memory");
}

#define LDSM4(r0, r1, r2, r3, addr) \
    asm volatile("ldmatrix.sync.aligned.m8n8.x4.shared.b16 {%0,%1,%2,%3}, [%4];" \
                 : "=r"(r0), "=r"(r1), "=r"(r2), "=r"(r3) : "r"(addr))

#define LDSM4T(r0, r1, r2, r3, addr) \
    asm volatile("ldmatrix.sync.aligned.m8n8.x4.trans.shared.b16 {%0,%1,%2,%3}, [%4];" \
                 : "=r"(r0), "=r"(r1), "=r"(r2), "=r"(r3) : "r"(addr))

__device__ __forceinline__ void hmma(float* c,
    uint32_t a0, uint32_t a1, uint32_t a2, uint32_t a3, uint32_t b0, uint32_t b1)
{
    asm volatile(
        "mma.sync.aligned.m16n8k16.row.col.f32.f16.f16.f32 "
        "{%0,%1,%2,%3}, {%4,%5,%6,%7}, {%8,%9}, {%0,%1,%2,%3};"
        : "+f"(c[0]), "+f"(c[1]), "+f"(c[2]), "+f"(c[3])
        : "r"(a0), "r"(a1), "r"(a2), "r"(a3), "r"(b0), "r"(b1));
}

__device__ __forceinline__ float gelu_f(float x) {
    float x3 = x * x * x;
    float t = tanhf(0.7978845608028654f * (x + 0.044715f * x3));
    return 0.5f * x * (1.0f + t);
}

// ---------------- fp16 tensor-core GEMM (exact R7 shape) ----------------
#define BM 128
#define BN 128
#define BKH 64
#define NST 3
#define STAGE_A_BYTES (BM * BKH * 2)
#define STAGE_B_BYTES (BN * BKH * 2)
#define STG_BYTES (STAGE_A_BYTES + STAGE_B_BYTES)
#define HGEMM_SMEM (STG_BYTES * NST)

#define EPI_BIAS       0
#define EPI_BIAS_GELU  1
#define EPI_BIAS_RESID 2

__device__ __forceinline__ void hload_chunk(
    uint32_t sA, uint32_t sB, const __half* __restrict__ A,
    const __half* __restrict__ BT, int m0, int n0, int k0, int K, int tid)
{
    #pragma unroll
    for (int i = 0; i < 4; i++) {
        int f = tid + 256 * i;
        int r = f >> 3, c = f & 7;
        cp16(sA + SW128(r * 128 + c * 16), A + (size_t)(m0 + r) * K + k0 + c * 8);
    }
    #pragma unroll
    for (int i = 0; i < 4; i++) {
        int f = tid + 256 * i;
        int r = f >> 3, c = f & 7;
        cp16(sB + SW128(r * 128 + c * 16), BT + (size_t)(n0 + r) * K + k0 + c * 8);
    }
    asm volatile("cp.async.commit_group;" ::: "memory");
}

template <typename OutT>
__device__ __forceinline__ void store_pair(OutT* p, float v0, float v1);
template <>
__device__ __forceinline__ void store_pair<float>(float* p, float v0, float v1) {
    *(float2*)p = make_float2(v0, v1);
}
template <>
__device__ __forceinline__ void store_pair<__half>(__half* p, float v0, float v1) {
    *(__half2*)p = __floats2half2_rn(v0, v1);
}

template <int EPI, typename OutT>
__global__ __launch_bounds__(256, 2) void hgemm(
    const __half* __restrict__ A, const __half* __restrict__ BT,
    const float* __restrict__ bias, const float* __restrict__ resid,
    OutT* __restrict__ C, int M, int N, int K)
{
    extern __shared__ char sm_raw[];
    const uint32_t sbase = smem_u32(sm_raw);

    const int tid = threadIdx.x;
    const int lane = tid & 31, wid = tid >> 5;
    const int wm = (wid >> 2) * 64;
    const int wn = (wid & 3) * 32;
    const int m0 = blockIdx.y * BM, n0 = blockIdx.x * BN;

    const int a_hi = lane >> 4;
    const int b_hi = (lane >> 3) & 1;
    int arow[4], brow[2];
    #pragma unroll
    for (int mt = 0; mt < 4; mt++) arow[mt] = wm + mt * 16 + (lane & 15);
    #pragma unroll
    for (int p = 0; p < 2; p++)
        brow[p] = wn + p * 16 + ((lane >> 4) << 3) + (lane & 7);

    float acc[4][4][4];
    #pragma unroll
    for (int mt = 0; mt < 4; mt++)
        #pragma unroll
        for (int nt = 0; nt < 4; nt++)
            #pragma unroll
            for (int i = 0; i < 4; i++) acc[mt][nt][i] = 0.f;

    const int nc = K / BKH;

    hload_chunk(sbase, sbase + STAGE_A_BYTES, A, BT, m0, n0, 0, K, tid);
    hload_chunk(sbase + STG_BYTES, sbase + STG_BYTES + STAGE_A_BYTES,
                A, BT, m0, n0, BKH, K, tid);

    for (int k = 0; k < nc; k++) {
        const uint32_t sA = sbase + (k % NST) * STG_BYTES;
        const uint32_t sB = sA + STAGE_A_BYTES;

        asm volatile("cp.async.wait_group 1;" ::: "memory");
        __syncthreads();

        if (k + 2 < nc) {
            const uint32_t pA = sbase + ((k + 2) % NST) * STG_BYTES;
            hload_chunk(pA, pA + STAGE_A_BYTES, A, BT, m0, n0, (k + 2) * BKH, K, tid);
        } else {
            asm volatile("cp.async.commit_group;" ::: "memory");
        }

        #pragma unroll
        for (int kk = 0; kk < 4; kk++) {
            uint32_t af[4][4];
            #pragma unroll
            for (int mt = 0; mt < 4; mt++) {
                const int row = arow[mt];
                const uint32_t addr =
                    sA + row * 128 + ((((kk << 1) + a_hi) ^ (row & 7)) << 4);
                LDSM4(af[mt][0], af[mt][1], af[mt][2], af[mt][3], addr);
            }
            uint32_t bf[4][2];
            #pragma unroll
            for (int p = 0; p < 2; p++) {
                const int row = brow[p];
                const uint32_t addr =
                    sB + row * 128 + ((((kk << 1) + b_hi) ^ (row & 7)) << 4);
                uint32_t r0, r1, r2, r3;
                LDSM4(r0, r1, r2, r3, addr);
                bf[2 * p][0] = r0; bf[2 * p][1] = r1;
                bf[2 * p + 1][0] = r2; bf[2 * p + 1][1] = r3;
            }
            #pragma unroll
            for (int mt = 0; mt < 4; mt++)
                #pragma unroll
                for (int nt = 0; nt < 4; nt++)
                    hmma(acc[mt][nt], af[mt][0], af[mt][1], af[mt][2], af[mt][3],
                         bf[nt][0], bf[nt][1]);
        }
    }

    const int g = lane >> 2, q = lane & 3;
    #pragma unroll
    for (int mt = 0; mt < 4; mt++) {
        #pragma unroll
        for (int nt = 0; nt < 4; nt++) {
            const int col = n0 + wn + nt * 8 + 2 * q;
            const float2 bv = *(const float2*)(bias + col);
            #pragma unroll
            for (int hh = 0; hh < 2; hh++) {
                const int row = m0 + wm + mt * 16 + g + hh * 8;
                float v0 = acc[mt][nt][2 * hh]     + bv.x;
                float v1 = acc[mt][nt][2 * hh + 1] + bv.y;
                if (EPI == EPI_BIAS_GELU) { v0 = gelu_f(v0); v1 = gelu_f(v1); }
                if (EPI == EPI_BIAS_RESID) {
                    const float2 rv = *(const float2*)(resid + (size_t)row * N + col);
                    v0 += rv.x; v1 += rv.y;
                }
                store_pair<OutT>(C + (size_t)row * N + col, v0, v1);
            }
        }
    }
}

// ---------------- weight transpose: W[K,N] fp32 -> WT[N,K] fp16 ----------------
// 64(K) x 32(N) tile, 256 threads; coalesced float loads, half2 stores (128B/warp).
__global__ __launch_bounds__(256) void transpose_kernel(
    const float* __restrict__ W, __half* __restrict__ WT, int K, int N)
{
    __shared__ float t[64][33];
    const int nx = blockIdx.x * 32, kx = blockIdx.y * 64;
    const int tid = threadIdx.x;
    const int lane = tid & 31, w = tid >> 5;

    #pragma unroll
    for (int i = 0; i < 8; i++) {
        int f = tid + 256 * i;          // 0..2047
        int r = f >> 5, c = f & 31;     // 64 rows x 32 cols
        t[r][c] = W[(size_t)(kx + r) * N + nx + c];
    }
    __syncthreads();

    #pragma unroll
    for (int i = 0; i < 4; i++) {
        const int n = w + i * 8;        // 32 output rows
        __half2 v = __floats2half2_rn(t[2 * lane][n], t[2 * lane + 1][n]);
        *(__half2*)(WT + (size_t)(nx + n) * K + kx + 2 * lane) = v;
    }
}

// ---------------- LayerNorm (fp32 in, fp16 out) ----------------
__global__ __launch_bounds__(256) void ln_kernel(
    const float* __restrict__ x, const float* __restrict__ g,
    const float* __restrict__ b, __half* __restrict__ o)
{
    const int row = blockIdx.x;
    const float* xr = x + (size_t)row * HID;
    __half* orow = o + (size_t)row * HID;
    const int tid = threadIdx.x;

    float4 v0 = *(const float4*)(xr + tid * 4);
    float4 v1 = *(const float4*)(xr + 1024 + tid * 4);

    float s = v0.x + v0.y + v0.z + v0.w + v1.x + v1.y + v1.z + v1.w;
    float q = v0.x*v0.x + v0.y*v0.y + v0.z*v0.z + v0.w*v0.w
            + v1.x*v1.x + v1.y*v1.y + v1.z*v1.z + v1.w*v1.w;

    #pragma unroll
    for (int off = 16; off; off >>= 1) {
        s += __shfl_xor_sync(0xffffffffu, s, off);
        q += __shfl_xor_sync(0xffffffffu, q, off);
    }
    __shared__ float ss[8], sq[8];
    __shared__ float stats[2];
    const int wid = tid >> 5, lane = tid & 31;
    if (lane == 0) { ss[wid] = s; sq[wid] = q; }
    __syncthreads();
    if (tid == 0) {
        float S = 0.f, Q = 0.f;
        #pragma unroll
        for (int w = 0; w < 8; w++) { S += ss[w]; Q += sq[w]; }
        float mu = S * (1.0f / HID);
        float var = Q * (1.0f / HID) - mu * mu;
        stats[0] = mu;
        stats[1] = rsqrtf(var + 1e-5f);
    }
    __syncthreads();
    const float mu = stats[0], rs = stats[1];

    float4 g0 = *(const float4*)(g + tid * 4);
    float4 g1 = *(const float4*)(g + 1024 + tid * 4);
    float4 b0 = *(const float4*)(b + tid * 4);
    float4 b1 = *(const float4*)(b + 1024 + tid * 4);

    __half2 h0[2], h1[2];
    h0[0] = __floats2half2_rn((v0.x - mu) * rs * g0.x + b0.x,
                              (v0.y - mu) * rs * g0.y + b0.y);
    h0[1] = __floats2half2_rn((v0.z - mu) * rs * g0.z + b0.z,
                              (v0.w - mu) * rs * g0.w + b0.w);
    h1[0] = __floats2half2_rn((v1.x - mu) * rs * g1.x + b1.x,
                              (v1.y - mu) * rs * g1.y + b1.y);
    h1[1] = __floats2half2_rn((v1.z - mu) * rs * g1.z + b1.z,
                              (v1.w - mu) * rs * g1.w + b1.w);
    *(uint2*)(orow + tid * 4)        = *(uint2*)h0;
    *(uint2*)(orow + 1024 + tid * 4) = *(uint2*)h1;
}

// ---------------- fp16 tensor-core flash attention (causal) ----------------
#define AQ 128
#define AKV 64
#define ATT_Q_BYTES  (AQ * 256)
#define ATT_KV_BYTES (AKV * 256)
#define ATT_SMEM (ATT_Q_BYTES + 4 * ATT_KV_BYTES)

__device__ __forceinline__ uint32_t sw_row256(uint32_t base, int row, int u) {
    return base + row * 256 + ((u >> 3) << 7) + ((((u & 7) ^ (row & 7))) << 4);
}

__global__ __launch_bounds__(256) void attn_kernel(
    const __half* __restrict__ qkv, __half* __restrict__ out)
{
    extern __shared__ char asm_raw[];
    const uint32_t sbase = smem_u32(asm_raw);
    const uint32_t sQ = sbase;
    const uint32_t sK0 = sbase + ATT_Q_BYTES;
    const uint32_t sK1 = sK0 + ATT_KV_BYTES;
    const uint32_t sV0 = sK1 + ATT_KV_BYTES;
    const uint32_t sV1 = sV0 + ATT_KV_BYTES;

    const int qb = blockIdx.x, h = blockIdx.y, bb = blockIdx.z;
    const int tid = threadIdx.x;
    const int lane = tid & 31, wid = tid >> 5;
    const int q0 = qb * AQ;
    const float SC = 0.08838834764831845f;
    const size_t base = (size_t)bb * SEQ * (3 * HID) + (size_t)h * HDIM;

    #pragma unroll
    for (int i = 0; i < 8; i++) {
        int f = tid + 256 * i;
        int r = f >> 4, u = f & 15;
        cp16(sw_row256(sQ, r, u), qkv + base + (size_t)(q0 + r) * (3 * HID) + u * 8);
    }
    asm volatile("cp.async.commit_group;" ::: "memory");
    asm volatile("cp.async.wait_group 0;" ::: "memory");
    __syncthreads();

    const int nkb = qb * 2 + 2;

    {
        #pragma unroll
        for (int i = 0; i < 4; i++) {
            int f = tid + 256 * i;
            int r = f >> 4, u = f & 15;
            const __half* src = qkv + base + (size_t)r * (3 * HID) + u * 8;
            cp16(sw_row256(sK0, r, u), src + HID);
            cp16(sw_row256(sV0, r, u), src + 2 * HID);
        }
        asm volatile("cp.async.commit_group;" ::: "memory");
        #pragma unroll
        for (int i = 0; i < 4; i++) {
            int f = tid + 256 * i;
            int r = f >> 4, u = f & 15;
            const __half* src = qkv + base + (size_t)(AKV + r) * (3 * HID) + u * 8;
            cp16(sw_row256(sK1, r, u), src + HID);
            cp16(sw_row256(sV1, r, u), src + 2 * HID);
        }
        asm volatile("cp.async.commit_group;" ::: "memory");
    }

    const int g = lane >> 2, q2 = (lane & 3) * 2;
    const int wq = wid * 16;
    const int arow = wq + (lane & 15);
    const int a_hi = lane >> 4;
    const int b_hi = (lane >> 3) & 1;

    const int qrow0 = q0 + wq + g;
    const int qrow1 = qrow0 + 8;

    float m0 = -1e30f, m1 = -1e30f, l0 = 0.f, l1 = 0.f;
    float o[16][4];
    #pragma unroll
    for (int nt = 0; nt < 16; nt++)
        #pragma unroll
        for (int i = 0; i < 4; i++) o[nt][i] = 0.f;

    for (int kb = 0; kb < nkb; kb++) {
        const uint32_t sK = (kb & 1) ? sK1 : sK0;
        const uint32_t sV = (kb & 1) ? sV1 : sV0;

        asm volatile("cp.async.wait_group 1;" ::: "memory");
        __syncthreads();

        float sacc[8][4];
        #pragma unroll
        for (int nt = 0; nt < 8; nt++)
            #pragma unroll
            for (int i = 0; i < 4; i++) sacc[nt][i] = 0.f;

        #pragma unroll
        for (int kk = 0; kk < 8; kk++) {
            uint32_t a0, a1, a2, a3;
            LDSM4(a0, a1, a2, a3, sw_row256(sQ, arow, (kk << 1) + a_hi));
            #pragma unroll
            for (int p = 0; p < 2; p++) {
                const int row0 = p * 32 + ((lane >> 4) << 3) + (lane & 7);
                uint32_t r0, r1, r2, r3;
                LDSM4(r0, r1, r2, r3, sw_row256(sK, row0, (kk << 1) + b_hi));
                hmma(sacc[4 * p + 0], a0, a1, a2, a3, r0, r1);
                hmma(sacc[4 * p + 1], a0, a1, a2, a3, r2, r3);
                const int row1 = row0 + 16;
                LDSM4(r0, r1, r2, r3, sw_row256(sK, row1, (kk << 1) + b_hi));
                hmma(sacc[4 * p + 2], a0, a1, a2, a3, r0, r1);
                hmma(sacc[4 * p + 3], a0, a1, a2, a3, r2, r3);
            }
        }

        const bool need_mask = (kb * AKV + AKV - 1) > (q0 + wq);
        float mt0 = -1e30f, mt1 = -1e30f;
        #pragma unroll
        for (int nt = 0; nt < 8; nt++) {
            const int key = kb * AKV + nt * 8 + q2;
            float s0 = sacc[nt][0] * SC, s1 = sacc[nt][1] * SC;
            float s2 = sacc[nt][2] * SC, s3 = sacc[nt][3] * SC;
            if (need_mask) {
                if (key     > qrow0) s0 = -1e30f;
                if (key + 1 > qrow0) s1 = -1e30f;
                if (key     > qrow1) s2 = -1e30f;
                if (key + 1 > qrow1) s3 = -1e30f;
            }
            sacc[nt][0] = s0; sacc[nt][1] = s1;
            sacc[nt][2] = s2; sacc[nt][3] = s3;
            mt0 = fmaxf(mt0, fmaxf(s0, s1));
            mt1 = fmaxf(mt1, fmaxf(s2, s3));
        }
        mt0 = fmaxf(mt0, __shfl_xor_sync(0xffffffffu, mt0, 1));
        mt0 = fmaxf(mt0, __shfl_xor_sync(0xffffffffu, mt0, 2));
        mt1 = fmaxf(mt1, __shfl_xor_sync(0xffffffffu, mt1, 1));
        mt1 = fmaxf(mt1, __shfl_xor_sync(0xffffffffu, mt1, 2));

        const float mn0 = fmaxf(m0, mt0), mn1 = fmaxf(m1, mt1);
        const float fs0 = __expf(m0 - mn0), fs1 = __expf(m1 - mn1);
        m0 = mn0; m1 = mn1;

        uint32_t p01[8], p23[8];
        float rs0 = 0.f, rs1 = 0.f;
        #pragma unroll
        for (int nt = 0; nt < 8; nt++) {
            float e0 = __expf(sacc[nt][0] - mn0);
            float e1 = __expf(sacc[nt][1] - mn0);
            float e2 = __expf(sacc[nt][2] - mn1);
            float e3 = __expf(sacc[nt][3] - mn1);
            rs0 += e0 + e1; rs1 += e2 + e3;
            p01[nt] = h2_to_u32(__floats2half2_rn(e0, e1));
            p23[nt] = h2_to_u32(__floats2half2_rn(e2, e3));
        }
        rs0 += __shfl_xor_sync(0xffffffffu, rs0, 1);
        rs0 += __shfl_xor_sync(0xffffffffu, rs0, 2);
        rs1 += __shfl_xor_sync(0xffffffffu, rs1, 1);
        rs1 += __shfl_xor_sync(0xffffffffu, rs1, 2);
        l0 = l0 * fs0 + rs0;
        l1 = l1 * fs1 + rs1;

        #pragma unroll
        for (int nt = 0; nt < 16; nt++) {
            o[nt][0] *= fs0; o[nt][1] *= fs0;
            o[nt][2] *= fs1; o[nt][3] *= fs1;
        }

        #pragma unroll
        for (int kt = 0; kt < 4; kt++) {
            const uint32_t a0 = p01[2 * kt], a1 = p23[2 * kt];
            const uint32_t a2 = p01[2 * kt + 1], a3 = p23[2 * kt + 1];
            const int vkey = kt * 16 + (lane & 15);
            #pragma unroll
            for (int ndp = 0; ndp < 8; ndp++) {
                const int d = ndp * 16 + ((lane >> 4) << 3);
                uint32_t r0, r1, r2, r3;
                LDSM4T(r0, r1, r2, r3, sw_row256(sV, vkey, d >> 3));
                hmma(o[2 * ndp],     a0, a1, a2, a3, r0, r1);
                hmma(o[2 * ndp + 1], a0, a1, a2, a3, r2, r3);
            }
        }

        __syncthreads();

        if (kb + 2 < nkb) {
            const uint32_t pK = (kb & 1) ? sK1 : sK0;
            const uint32_t pV = (kb & 1) ? sV1 : sV0;
            const int k0n = (kb + 2) * AKV;
            #pragma unroll
            for (int i = 0; i < 4; i++) {
                int f = tid + 256 * i;
                int r = f >> 4, u = f & 15;
                const __half* src = qkv + base + (size_t)(k0n + r) * (3 * HID) + u * 8;
                cp16(sw_row256(pK, r, u), src + HID);
                cp16(sw_row256(pV, r, u), src + 2 * HID);
            }
        }
        asm volatile("cp.async.commit_group;" ::: "memory");
    }

    const float inv0 = 1.0f / l0, inv1 = 1.0f / l1;
    __half* ob = out + ((size_t)bb * SEQ) * HID + (size_t)h * HDIM;
    #pragma unroll
    for (int nt = 0; nt < 16; nt++) {
        const int col = nt * 8 + q2;
        *(__half2*)(ob + (size_t)(q0 + wq + g) * HID + col) =
            __floats2half2_rn(o[nt][0] * inv0, o[nt][1] * inv0);
        *(__half2*)(ob + (size_t)(q0 + wq + g + 8) * HID + col) =
            __floats2half2_rn(o[nt][2] * inv1, o[nt][3] * inv1);
    }
}

// ---------------- host ----------------
extern "C" void kernel_launch(void* const* d_in, const int* in_sizes, int n_in,
                              void* d_out, int out_size)
{
    const float* x     = (const float*)d_in[0];
    const float* ln1_g = (const float*)d_in[1];
    const float* ln1_b = (const float*)d_in[2];
    const float* ln2_g = (const float*)d_in[3];
    const float* ln2_b = (const float*)d_in[4];
    const float* w_qkv = (const float*)d_in[5];
    const float* b_qkv = (const float*)d_in[6];
    const float* w_ao  = (const float*)d_in[7];
    const float* b_ao  = (const float*)d_in[8];
    const float* w_ff1 = (const float*)d_in[9];
    const float* b_ff1 = (const float*)d_in[10];
    const float* w_ff2 = (const float*)d_in[11];
    const float* b_ff2 = (const float*)d_in[12];
    float* out = (float*)d_out;

    __half *h, *qkv, *attn, *ffb, *wt_qkv, *wt_ao, *wt_ff1, *wt_ff2;
    float *x1;
    cudaGetSymbolAddress((void**)&h,      g_h);
    cudaGetSymbolAddress((void**)&qkv,    g_qkv);
    cudaGetSymbolAddress((void**)&attn,   g_attn);
    cudaGetSymbolAddress((void**)&x1,     g_x1);
    cudaGetSymbolAddress((void**)&ffb,    g_ff);
    cudaGetSymbolAddress((void**)&wt_qkv, g_wt_qkv);
    cudaGetSymbolAddress((void**)&wt_ao,  g_wt_ao);
    cudaGetSymbolAddress((void**)&wt_ff1, g_wt_ff1);
    cudaGetSymbolAddress((void**)&wt_ff2, g_wt_ff2);

    cudaFuncSetAttribute(attn_kernel,
                         cudaFuncAttributeMaxDynamicSharedMemorySize, ATT_SMEM);
    cudaFuncSetAttribute(hgemm<EPI_BIAS, __half>,
                         cudaFuncAttributeMaxDynamicSharedMemorySize, HGEMM_SMEM);
    cudaFuncSetAttribute(hgemm<EPI_BIAS_GELU, __half>,
                         cudaFuncAttributeMaxDynamicSharedMemorySize, HGEMM_SMEM);
    cudaFuncSetAttribute(hgemm<EPI_BIAS_RESID, float>,
                         cudaFuncAttributeMaxDynamicSharedMemorySize, HGEMM_SMEM);

    // 0) transpose + convert weights to fp16 [N, K]  (64K x 32N tiles)
    transpose_kernel<<<dim3(3 * HID / 32, HID / 64), 256>>>(w_qkv, wt_qkv, HID, 3 * HID);
    transpose_kernel<<<dim3(HID / 32, HID / 64),     256>>>(w_ao,  wt_ao,  HID, HID);
    transpose_kernel<<<dim3(FF / 32, HID / 64),      256>>>(w_ff1, wt_ff1, HID, FF);
    transpose_kernel<<<dim3(HID / 32, FF / 64),      256>>>(w_ff2, wt_ff2, FF, HID);

    // 1) LN1 -> fp16
    ln_kernel<<<TOK, 256>>>(x, ln1_g, ln1_b, h);
    // 2) QKV = h @ w_qkv + b_qkv  (fp16 out)
    hgemm<EPI_BIAS, __half><<<dim3(3 * HID / BN, TOK / BM), 256, HGEMM_SMEM>>>(
        h, wt_qkv, b_qkv, nullptr, qkv, TOK, 3 * HID, HID);
    // 3) attention (fp16 tensor cores, fp16 out)
    attn_kernel<<<dim3(SEQ / AQ, NHEAD, BATCH), 256, ATT_SMEM>>>(qkv, attn);
    // 4) x1 = x + attn @ w_ao + b_ao  (fp32 out)
    hgemm<EPI_BIAS_RESID, float><<<dim3(HID / BN, TOK / BM), 256, HGEMM_SMEM>>>(
        attn, wt_ao, b_ao, x, x1, TOK, HID, HID);
    // 5) LN2 -> fp16
    ln_kernel<<<TOK, 256>>>(x1, ln2_g, ln2_b, h);
    // 6) ff = gelu(h @ w_ff1 + b_ff1)  (fp16 out)
    hgemm<EPI_BIAS_GELU, __half><<<dim3(FF / BN, TOK / BM), 256, HGEMM_SMEM>>>(
        h, wt_ff1, b_ff1, nullptr, ffb, TOK, FF, HID);
    // 7) out = x1 + ff @ w_ff2 + b_ff2  (fp32 out)
    hgemm<EPI_BIAS_RESID, float><<<dim3(HID / BN, TOK / BM), 256, HGEMM_SMEM>>>(
        ffb, wt_ff2, b_ff2, x1, out, TOK, HID, FF);
}

// round 17
// speedup vs baseline: 1.5587x; 1.0011x over previous
#include <cuda_runtime.h>
#include <cuda_fp16.h>
#include <cstdint>
#include <math.h>

// Problem constants
#define BATCH 2
#define SEQ   2048
#define HID   2048
#define NHEAD 16
#define HDIM  128
#define TOK   (BATCH * SEQ)      // 4096 rows
#define FF    (4 * HID)          // 8192

// ---------------- scratch (device globals; no allocation) ----------------
__device__ __align__(256) __half g_h   [TOK * HID];       // LN out (fp16)
__device__ __align__(256) __half g_qkv [TOK * 3 * HID];   // QKV (fp16)
__device__ __align__(256) __half g_attn[TOK * HID];       // attn out (fp16)
__device__ float                 g_x1  [TOK * HID];       // residual-1 (fp32)
__device__ __align__(256) __half g_ff  [TOK * FF];        // gelu(ff1) (fp16)
// transposed weights [N, K] fp16
__device__ __align__(256) __half g_wt_qkv[3 * HID * HID];
__device__ __align__(256) __half g_wt_ao [HID * HID];
__device__ __align__(256) __half g_wt_ff1[FF * HID];
__device__ __align__(256) __half g_wt_ff2[HID * FF];

// ---------------- helpers ----------------
__device__ __forceinline__ uint32_t smem_u32(const void* p) {
    uint32_t a;
    asm("{ .reg .u64 t; cvta.to.shared.u64 t, %1; cvt.u32.u64 %0, t; }"
        : "=r"(a) : "l"(p));
    return a;
}
#define SW128(o) ((o) ^ (((o) >> 3) & 0x70))

__device__ __forceinline__ uint32_t h2_to_u32(__half2 h) {
    return *reinterpret_cast<uint32_t*>(&h);
}

__device__ __forceinline__ void cp16(uint32_t dst, const void* src) {
    asm volatile("cp.async.cg.shared.global [%0], [%1], 16;"
                 :: "r"(dst), "l"(src) : "memory");
}

#define LDSM4(r0, r1, r2, r3, addr) \
    asm volatile("ldmatrix.sync.aligned.m8n8.x4.shared.b16 {%0,%1,%2,%3}, [%4];" \
                 : "=r"(r0), "=r"(r1), "=r"(r2), "=r"(r3) : "r"(addr))

#define LDSM4T(r0, r1, r2, r3, addr) \
    asm volatile("ldmatrix.sync.aligned.m8n8.x4.trans.shared.b16 {%0,%1,%2,%3}, [%4];" \
                 : "=r"(r0), "=r"(r1), "=r"(r2), "=r"(r3) : "r"(addr))

__device__ __forceinline__ void hmma(float* c,
    uint32_t a0, uint32_t a1, uint32_t a2, uint32_t a3, uint32_t b0, uint32_t b1)
{
    asm volatile(
        "mma.sync.aligned.m16n8k16.row.col.f32.f16.f16.f32 "
        "{%0,%1,%2,%3}, {%4,%5,%6,%7}, {%8,%9}, {%0,%1,%2,%3};"
        : "+f"(c[0]), "+f"(c[1]), "+f"(c[2]), "+f"(c[3])
        : "r"(a0), "r"(a1), "r"(a2), "r"(a3), "r"(b0), "r"(b1));
}

__device__ __forceinline__ float gelu_f(float x) {
    float x3 = x * x * x;
    float t = tanhf(0.7978845608028654f * (x + 0.044715f * x3));
    return 0.5f * x * (1.0f + t);
}

// ---------------- fp16 tensor-core GEMM (exact R7 shape) ----------------
#define BM 128
#define BN 128
#define BKH 64
#define NST 3
#define STAGE_A_BYTES (BM * BKH * 2)
#define STAGE_B_BYTES (BN * BKH * 2)
#define STG_BYTES (STAGE_A_BYTES + STAGE_B_BYTES)
#define HGEMM_SMEM (STG_BYTES * NST)

#define EPI_BIAS       0
#define EPI_BIAS_GELU  1
#define EPI_BIAS_RESID 2

__device__ __forceinline__ void hload_chunk(
    uint32_t sA, uint32_t sB, const __half* __restrict__ A,
    const __half* __restrict__ BT, int m0, int n0, int k0, int K, int tid)
{
    #pragma unroll
    for (int i = 0; i < 4; i++) {
        int f = tid + 256 * i;
        int r = f >> 3, c = f & 7;
        cp16(sA + SW128(r * 128 + c * 16), A + (size_t)(m0 + r) * K + k0 + c * 8);
    }
    #pragma unroll
    for (int i = 0; i < 4; i++) {
        int f = tid + 256 * i;
        int r = f >> 3, c = f & 7;
        cp16(sB + SW128(r * 128 + c * 16), BT + (size_t)(n0 + r) * K + k0 + c * 8);
    }
    asm volatile("cp.async.commit_group;" ::: "memory");
}

template <typename OutT>
__device__ __forceinline__ void store_pair(OutT* p, float v0, float v1);
template <>
__device__ __forceinline__ void store_pair<float>(float* p, float v0, float v1) {
    *(float2*)p = make_float2(v0, v1);
}
template <>
__device__ __forceinline__ void store_pair<__half>(__half* p, float v0, float v1) {
    *(__half2*)p = __floats2half2_rn(v0, v1);
}

template <int EPI, typename OutT>
__global__ __launch_bounds__(256, 2) void hgemm(
    const __half* __restrict__ A, const __half* __restrict__ BT,
    const float* __restrict__ bias, const float* __restrict__ resid,
    OutT* __restrict__ C, int M, int N, int K)
{
    extern __shared__ char sm_raw[];
    const uint32_t sbase = smem_u32(sm_raw);

    const int tid = threadIdx.x;
    const int lane = tid & 31, wid = tid >> 5;
    const int wm = (wid >> 2) * 64;
    const int wn = (wid & 3) * 32;
    const int m0 = blockIdx.y * BM, n0 = blockIdx.x * BN;

    const int a_hi = lane >> 4;
    const int b_hi = (lane >> 3) & 1;
    int arow[4], brow[2];
    #pragma unroll
    for (int mt = 0; mt < 4; mt++) arow[mt] = wm + mt * 16 + (lane & 15);
    #pragma unroll
    for (int p = 0; p < 2; p++)
        brow[p] = wn + p * 16 + ((lane >> 4) << 3) + (lane & 7);

    float acc[4][4][4];
    #pragma unroll
    for (int mt = 0; mt < 4; mt++)
        #pragma unroll
        for (int nt = 0; nt < 4; nt++)
            #pragma unroll
            for (int i = 0; i < 4; i++) acc[mt][nt][i] = 0.f;

    const int nc = K / BKH;

    hload_chunk(sbase, sbase + STAGE_A_BYTES, A, BT, m0, n0, 0, K, tid);
    hload_chunk(sbase + STG_BYTES, sbase + STG_BYTES + STAGE_A_BYTES,
                A, BT, m0, n0, BKH, K, tid);

    for (int k = 0; k < nc; k++) {
        const uint32_t sA = sbase + (k % NST) * STG_BYTES;
        const uint32_t sB = sA + STAGE_A_BYTES;

        asm volatile("cp.async.wait_group 1;" ::: "memory");
        __syncthreads();

        if (k + 2 < nc) {
            const uint32_t pA = sbase + ((k + 2) % NST) * STG_BYTES;
            hload_chunk(pA, pA + STAGE_A_BYTES, A, BT, m0, n0, (k + 2) * BKH, K, tid);
        } else {
            asm volatile("cp.async.commit_group;" ::: "memory");
        }

        #pragma unroll
        for (int kk = 0; kk < 4; kk++) {
            uint32_t af[4][4];
            #pragma unroll
            for (int mt = 0; mt < 4; mt++) {
                const int row = arow[mt];
                const uint32_t addr =
                    sA + row * 128 + ((((kk << 1) + a_hi) ^ (row & 7)) << 4);
                LDSM4(af[mt][0], af[mt][1], af[mt][2], af[mt][3], addr);
            }
            uint32_t bf[4][2];
            #pragma unroll
            for (int p = 0; p < 2; p++) {
                const int row = brow[p];
                const uint32_t addr =
                    sB + row * 128 + ((((kk << 1) + b_hi) ^ (row & 7)) << 4);
                uint32_t r0, r1, r2, r3;
                LDSM4(r0, r1, r2, r3, addr);
                bf[2 * p][0] = r0; bf[2 * p][1] = r1;
                bf[2 * p + 1][0] = r2; bf[2 * p + 1][1] = r3;
            }
            #pragma unroll
            for (int mt = 0; mt < 4; mt++)
                #pragma unroll
                for (int nt = 0; nt < 4; nt++)
                    hmma(acc[mt][nt], af[mt][0], af[mt][1], af[mt][2], af[mt][3],
                         bf[nt][0], bf[nt][1]);
        }
    }

    const int g = lane >> 2, q = lane & 3;
    #pragma unroll
    for (int mt = 0; mt < 4; mt++) {
        #pragma unroll
        for (int nt = 0; nt < 4; nt++) {
            const int col = n0 + wn + nt * 8 + 2 * q;
            const float2 bv = *(const float2*)(bias + col);
            #pragma unroll
            for (int hh = 0; hh < 2; hh++) {
                const int row = m0 + wm + mt * 16 + g + hh * 8;
                float v0 = acc[mt][nt][2 * hh]     + bv.x;
                float v1 = acc[mt][nt][2 * hh + 1] + bv.y;
                if (EPI == EPI_BIAS_GELU) { v0 = gelu_f(v0); v1 = gelu_f(v1); }
                if (EPI == EPI_BIAS_RESID) {
                    const float2 rv = *(const float2*)(resid + (size_t)row * N + col);
                    v0 += rv.x; v1 += rv.y;
                }
                store_pair<OutT>(C + (size_t)row * N + col, v0, v1);
            }
        }
    }
}

// ---------------- weight transpose: W[K,N] fp32 -> WT[N,K] fp16 ----------------
// 64(K) x 32(N) tile, 256 threads; coalesced float loads, half2 stores (128B/warp).
__global__ __launch_bounds__(256) void transpose_kernel(
    const float* __restrict__ W, __half* __restrict__ WT, int K, int N)
{
    __shared__ float t[64][33];
    const int nx = blockIdx.x * 32, kx = blockIdx.y * 64;
    const int tid = threadIdx.x;
    const int lane = tid & 31, w = tid >> 5;

    #pragma unroll
    for (int i = 0; i < 8; i++) {
        int f = tid + 256 * i;
        int r = f >> 5, c = f & 31;
        t[r][c] = W[(size_t)(kx + r) * N + nx + c];
    }
    __syncthreads();

    #pragma unroll
    for (int i = 0; i < 4; i++) {
        const int n = w + i * 8;
        __half2 v = __floats2half2_rn(t[2 * lane][n], t[2 * lane + 1][n]);
        *(__half2*)(WT + (size_t)(nx + n) * K + kx + 2 * lane) = v;
    }
}

// ---------------- LayerNorm (fp32 in, fp16 out) ----------------
__global__ __launch_bounds__(256) void ln_kernel(
    const float* __restrict__ x, const float* __restrict__ g,
    const float* __restrict__ b, __half* __restrict__ o)
{
    const int row = blockIdx.x;
    const float* xr = x + (size_t)row * HID;
    __half* orow = o + (size_t)row * HID;
    const int tid = threadIdx.x;

    float4 v0 = *(const float4*)(xr + tid * 4);
    float4 v1 = *(const float4*)(xr + 1024 + tid * 4);

    float s = v0.x + v0.y + v0.z + v0.w + v1.x + v1.y + v1.z + v1.w;
    float q = v0.x*v0.x + v0.y*v0.y + v0.z*v0.z + v0.w*v0.w
            + v1.x*v1.x + v1.y*v1.y + v1.z*v1.z + v1.w*v1.w;

    #pragma unroll
    for (int off = 16; off; off >>= 1) {
        s += __shfl_xor_sync(0xffffffffu, s, off);
        q += __shfl_xor_sync(0xffffffffu, q, off);
    }
    __shared__ float ss[8], sq[8];
    __shared__ float stats[2];
    const int wid = tid >> 5, lane = tid & 31;
    if (lane == 0) { ss[wid] = s; sq[wid] = q; }
    __syncthreads();
    if (tid == 0) {
        float S = 0.f, Q = 0.f;
        #pragma unroll
        for (int w = 0; w < 8; w++) { S += ss[w]; Q += sq[w]; }
        float mu = S * (1.0f / HID);
        float var = Q * (1.0f / HID) - mu * mu;
        stats[0] = mu;
        stats[1] = rsqrtf(var + 1e-5f);
    }
    __syncthreads();
    const float mu = stats[0], rs = stats[1];

    float4 g0 = *(const float4*)(g + tid * 4);
    float4 g1 = *(const float4*)(g + 1024 + tid * 4);
    float4 b0 = *(const float4*)(b + tid * 4);
    float4 b1 = *(const float4*)(b + 1024 + tid * 4);

    __half2 h0[2], h1[2];
    h0[0] = __floats2half2_rn((v0.x - mu) * rs * g0.x + b0.x,
                              (v0.y - mu) * rs * g0.y + b0.y);
    h0[1] = __floats2half2_rn((v0.z - mu) * rs * g0.z + b0.z,
                              (v0.w - mu) * rs * g0.w + b0.w);
    h1[0] = __floats2half2_rn((v1.x - mu) * rs * g1.x + b1.x,
                              (v1.y - mu) * rs * g1.y + b1.y);
    h1[1] = __floats2half2_rn((v1.z - mu) * rs * g1.z + b1.z,
                              (v1.w - mu) * rs * g1.w + b1.w);
    *(uint2*)(orow + tid * 4)        = *(uint2*)h0;
    *(uint2*)(orow + 1024 + tid * 4) = *(uint2*)h1;
}

// ---------------- fp16 tensor-core flash attention (causal) ----------------
// 3-stage K/V pipeline: prefetch of tile kb+2 is issued BEFORE the compute of
// tile kb (its target stage (kb+2)%3 == (kb-1)%3 was fully consumed in
// iteration kb-1, guaranteed by the top-of-loop __syncthreads()).
// wait_group invariant: exactly one commit per iteration (real or empty), so
// "wait_group 1" at the top of iteration kb drains tile kb's load.
#define AQ 128
#define AKV 64
#define ATT_Q_BYTES  (AQ * 256)
#define ATT_KV_BYTES (AKV * 256)
#define ATT_NSTG 3
#define ATT_SMEM (ATT_Q_BYTES + 2 * ATT_NSTG * ATT_KV_BYTES)   // 32KB + 96KB = 128KB

__device__ __forceinline__ uint32_t sw_row256(uint32_t base, int row, int u) {
    return base + row * 256 + ((u >> 3) << 7) + ((((u & 7) ^ (row & 7))) << 4);
}

__global__ __launch_bounds__(256) void attn_kernel(
    const __half* __restrict__ qkv, __half* __restrict__ out)
{
    extern __shared__ char asm_raw[];
    const uint32_t sbase = smem_u32(asm_raw);
    const uint32_t sQ = sbase;
    uint32_t sKs[ATT_NSTG], sVs[ATT_NSTG];
    #pragma unroll
    for (int s = 0; s < ATT_NSTG; s++) {
        sKs[s] = sbase + ATT_Q_BYTES + (2 * s)     * ATT_KV_BYTES;
        sVs[s] = sbase + ATT_Q_BYTES + (2 * s + 1) * ATT_KV_BYTES;
    }

    const int qb = blockIdx.x, h = blockIdx.y, bb = blockIdx.z;
    const int tid = threadIdx.x;
    const int lane = tid & 31, wid = tid >> 5;
    const int q0 = qb * AQ;
    const float SC = 0.08838834764831845f;
    const size_t base = (size_t)bb * SEQ * (3 * HID) + (size_t)h * HDIM;

    // ---- load Q tile ----
    #pragma unroll
    for (int i = 0; i < 8; i++) {
        int f = tid + 256 * i;
        int r = f >> 4, u = f & 15;
        cp16(sw_row256(sQ, r, u), qkv + base + (size_t)(q0 + r) * (3 * HID) + u * 8);
    }
    asm volatile("cp.async.commit_group;" ::: "memory");
    asm volatile("cp.async.wait_group 0;" ::: "memory");
    __syncthreads();

    const int nkb = qb * 2 + 2;

    // ---- prologue: load K/V tiles 0 and 1 (one commit group each) ----
    #pragma unroll
    for (int t = 0; t < 2; t++) {
        #pragma unroll
        for (int i = 0; i < 4; i++) {
            int f = tid + 256 * i;
            int r = f >> 4, u = f & 15;
            const __half* src = qkv + base + (size_t)(t * AKV + r) * (3 * HID) + u * 8;
            cp16(sw_row256(sKs[t], r, u), src + HID);
            cp16(sw_row256(sVs[t], r, u), src + 2 * HID);
        }
        asm volatile("cp.async.commit_group;" ::: "memory");
    }

    const int g = lane >> 2, q2 = (lane & 3) * 2;
    const int wq = wid * 16;
    const int arow = wq + (lane & 15);
    const int a_hi = lane >> 4;
    const int b_hi = (lane >> 3) & 1;

    const int qrow0 = q0 + wq + g;
    const int qrow1 = qrow0 + 8;

    float m0 = -1e30f, m1 = -1e30f, l0 = 0.f, l1 = 0.f;
    float o[16][4];
    #pragma unroll
    for (int nt = 0; nt < 16; nt++)
        #pragma unroll
        for (int i = 0; i < 4; i++) o[nt][i] = 0.f;

    for (int kb = 0; kb < nkb; kb++) {
        const int st = kb % ATT_NSTG;
        const uint32_t sK = sKs[st];
        const uint32_t sV = sVs[st];

        asm volatile("cp.async.wait_group 1;" ::: "memory");
        __syncthreads();

        // ---- early prefetch of tile kb+2 into stage (kb+2)%3 ----
        if (kb + 2 < nkb) {
            const int ps = (kb + 2) % ATT_NSTG;
            const int k0n = (kb + 2) * AKV;
            #pragma unroll
            for (int i = 0; i < 4; i++) {
                int f = tid + 256 * i;
                int r = f >> 4, u = f & 15;
                const __half* src = qkv + base + (size_t)(k0n + r) * (3 * HID) + u * 8;
                cp16(sw_row256(sKs[ps], r, u), src + HID);
                cp16(sw_row256(sVs[ps], r, u), src + 2 * HID);
            }
        }
        asm volatile("cp.async.commit_group;" ::: "memory");

        // ---- S = Q @ K^T ----
        float sacc[8][4];
        #pragma unroll
        for (int nt = 0; nt < 8; nt++)
            #pragma unroll
            for (int i = 0; i < 4; i++) sacc[nt][i] = 0.f;

        #pragma unroll
        for (int kk = 0; kk < 8; kk++) {
            uint32_t a0, a1, a2, a3;
            LDSM4(a0, a1, a2, a3, sw_row256(sQ, arow, (kk << 1) + a_hi));
            #pragma unroll
            for (int p = 0; p < 2; p++) {
                const int row0 = p * 32 + ((lane >> 4) << 3) + (lane & 7);
                uint32_t r0, r1, r2, r3;
                LDSM4(r0, r1, r2, r3, sw_row256(sK, row0, (kk << 1) + b_hi));
                hmma(sacc[4 * p + 0], a0, a1, a2, a3, r0, r1);
                hmma(sacc[4 * p + 1], a0, a1, a2, a3, r2, r3);
                const int row1 = row0 + 16;
                LDSM4(r0, r1, r2, r3, sw_row256(sK, row1, (kk << 1) + b_hi));
                hmma(sacc[4 * p + 2], a0, a1, a2, a3, r0, r1);
                hmma(sacc[4 * p + 3], a0, a1, a2, a3, r2, r3);
            }
        }

        const bool need_mask = (kb * AKV + AKV - 1) > (q0 + wq);
        float mt0 = -1e30f, mt1 = -1e30f;
        #pragma unroll
        for (int nt = 0; nt < 8; nt++) {
            const int key = kb * AKV + nt * 8 + q2;
            float s0 = sacc[nt][0] * SC, s1 = sacc[nt][1] * SC;
            float s2 = sacc[nt][2] * SC, s3 = sacc[nt][3] * SC;
            if (need_mask) {
                if (key     > qrow0) s0 = -1e30f;
                if (key + 1 > qrow0) s1 = -1e30f;
                if (key     > qrow1) s2 = -1e30f;
                if (key + 1 > qrow1) s3 = -1e30f;
            }
            sacc[nt][0] = s0; sacc[nt][1] = s1;
            sacc[nt][2] = s2; sacc[nt][3] = s3;
            mt0 = fmaxf(mt0, fmaxf(s0, s1));
            mt1 = fmaxf(mt1, fmaxf(s2, s3));
        }
        mt0 = fmaxf(mt0, __shfl_xor_sync(0xffffffffu, mt0, 1));
        mt0 = fmaxf(mt0, __shfl_xor_sync(0xffffffffu, mt0, 2));
        mt1 = fmaxf(mt1, __shfl_xor_sync(0xffffffffu, mt1, 1));
        mt1 = fmaxf(mt1, __shfl_xor_sync(0xffffffffu, mt1, 2));

        const float mn0 = fmaxf(m0, mt0), mn1 = fmaxf(m1, mt1);
        const float fs0 = __expf(m0 - mn0), fs1 = __expf(m1 - mn1);
        m0 = mn0; m1 = mn1;

        uint32_t p01[8], p23[8];
        float rs0 = 0.f, rs1 = 0.f;
        #pragma unroll
        for (int nt = 0; nt < 8; nt++) {
            float e0 = __expf(sacc[nt][0] - mn0);
            float e1 = __expf(sacc[nt][1] - mn0);
            float e2 = __expf(sacc[nt][2] - mn1);
            float e3 = __expf(sacc[nt][3] - mn1);
            rs0 += e0 + e1; rs1 += e2 + e3;
            p01[nt] = h2_to_u32(__floats2half2_rn(e0, e1));
            p23[nt] = h2_to_u32(__floats2half2_rn(e2, e3));
        }
        rs0 += __shfl_xor_sync(0xffffffffu, rs0, 1);
        rs0 += __shfl_xor_sync(0xffffffffu, rs0, 2);
        rs1 += __shfl_xor_sync(0xffffffffu, rs1, 1);
        rs1 += __shfl_xor_sync(0xffffffffu, rs1, 2);
        l0 = l0 * fs0 + rs0;
        l1 = l1 * fs1 + rs1;

        #pragma unroll
        for (int nt = 0; nt < 16; nt++) {
            o[nt][0] *= fs0; o[nt][1] *= fs0;
            o[nt][2] *= fs1; o[nt][3] *= fs1;
        }

        // ---- O += P @ V ----
        #pragma unroll
        for (int kt = 0; kt < 4; kt++) {
            const uint32_t a0 = p01[2 * kt], a1 = p23[2 * kt];
            const uint32_t a2 = p01[2 * kt + 1], a3 = p23[2 * kt + 1];
            const int vkey = kt * 16 + (lane & 15);
            #pragma unroll
            for (int ndp = 0; ndp < 8; ndp++) {
                const int d = ndp * 16 + ((lane >> 4) << 3);
                uint32_t r0, r1, r2, r3;
                LDSM4T(r0, r1, r2, r3, sw_row256(sV, vkey, d >> 3));
                hmma(o[2 * ndp],     a0, a1, a2, a3, r0, r1);
                hmma(o[2 * ndp + 1], a0, a1, a2, a3, r2, r3);
            }
        }
    }

    const float inv0 = 1.0f / l0, inv1 = 1.0f / l1;
    __half* ob = out + ((size_t)bb * SEQ) * HID + (size_t)h * HDIM;
    #pragma unroll
    for (int nt = 0; nt < 16; nt++) {
        const int col = nt * 8 + q2;
        *(__half2*)(ob + (size_t)(q0 + wq + g) * HID + col) =
            __floats2half2_rn(o[nt][0] * inv0, o[nt][1] * inv0);
        *(__half2*)(ob + (size_t)(q0 + wq + g + 8) * HID + col) =
            __floats2half2_rn(o[nt][2] * inv1, o[nt][3] * inv1);
    }
}

// ---------------- host ----------------
extern "C" void kernel_launch(void* const* d_in, const int* in_sizes, int n_in,
                              void* d_out, int out_size)
{
    const float* x     = (const float*)d_in[0];
    const float* ln1_g = (const float*)d_in[1];
    const float* ln1_b = (const float*)d_in[2];
    const float* ln2_g = (const float*)d_in[3];
    const float* ln2_b = (const float*)d_in[4];
    const float* w_qkv = (const float*)d_in[5];
    const float* b_qkv = (const float*)d_in[6];
    const float* w_ao  = (const float*)d_in[7];
    const float* b_ao  = (const float*)d_in[8];
    const float* w_ff1 = (const float*)d_in[9];
    const float* b_ff1 = (const float*)d_in[10];
    const float* w_ff2 = (const float*)d_in[11];
    const float* b_ff2 = (const float*)d_in[12];
    float* out = (float*)d_out;

    __half *h, *qkv, *attn, *ffb, *wt_qkv, *wt_ao, *wt_ff1, *wt_ff2;
    float *x1;
    cudaGetSymbolAddress((void**)&h,      g_h);
    cudaGetSymbolAddress((void**)&qkv,    g_qkv);
    cudaGetSymbolAddress((void**)&attn,   g_attn);
    cudaGetSymbolAddress((void**)&x1,     g_x1);
    cudaGetSymbolAddress((void**)&ffb,    g_ff);
    cudaGetSymbolAddress((void**)&wt_qkv, g_wt_qkv);
    cudaGetSymbolAddress((void**)&wt_ao,  g_wt_ao);
    cudaGetSymbolAddress((void**)&wt_ff1, g_wt_ff1);
    cudaGetSymbolAddress((void**)&wt_ff2, g_wt_ff2);

    cudaFuncSetAttribute(attn_kernel,
                         cudaFuncAttributeMaxDynamicSharedMemorySize, ATT_SMEM);
    cudaFuncSetAttribute(hgemm<EPI_BIAS, __half>,
                         cudaFuncAttributeMaxDynamicSharedMemorySize, HGEMM_SMEM);
    cudaFuncSetAttribute(hgemm<EPI_BIAS_GELU, __half>,
                         cudaFuncAttributeMaxDynamicSharedMemorySize, HGEMM_SMEM);
    cudaFuncSetAttribute(hgemm<EPI_BIAS_RESID, float>,
                         cudaFuncAttributeMaxDynamicSharedMemorySize, HGEMM_SMEM);

    // 0) transpose + convert weights to fp16 [N, K]  (64K x 32N tiles)
    transpose_kernel<<<dim3(3 * HID / 32, HID / 64), 256>>>(w_qkv, wt_qkv, HID, 3 * HID);
    transpose_kernel<<<dim3(HID / 32, HID / 64),     256>>>(w_ao,  wt_ao,  HID, HID);
    transpose_kernel<<<dim3(FF / 32, HID / 64),      256>>>(w_ff1, wt_ff1, HID, FF);
    transpose_kernel<<<dim3(HID / 32, FF / 64),      256>>>(w_ff2, wt_ff2, FF, HID);

    // 1) LN1 -> fp16
    ln_kernel<<<TOK, 256>>>(x, ln1_g, ln1_b, h);
    // 2) QKV = h @ w_qkv + b_qkv  (fp16 out)
    hgemm<EPI_BIAS, __half><<<dim3(3 * HID / BN, TOK / BM), 256, HGEMM_SMEM>>>(
        h, wt_qkv, b_qkv, nullptr, qkv, TOK, 3 * HID, HID);
    // 3) attention (fp16 tensor cores, fp16 out)
    attn_kernel<<<dim3(SEQ / AQ, NHEAD, BATCH), 256, ATT_SMEM>>>(qkv, attn);
    // 4) x1 = x + attn @ w_ao + b_ao  (fp32 out)
    hgemm<EPI_BIAS_RESID, float><<<dim3(HID / BN, TOK / BM), 256, HGEMM_SMEM>>>(
        attn, wt_ao, b_ao, x, x1, TOK, HID, HID);
    // 5) LN2 -> fp16
    ln_kernel<<<TOK, 256>>>(x1, ln2_g, ln2_b, h);
    // 6) ff = gelu(h @ w_ff1 + b_ff1)  (fp16 out)
    hgemm<EPI_BIAS_GELU, __half><<<dim3(FF / BN, TOK / BM), 256, HGEMM_SMEM>>>(
        h, wt_ff1, b_ff1, nullptr, ffb, TOK, FF, HID);
    // 7) out = x1 + ff @ w_ff2 + b_ff2  (fp32 out)
    hgemm<EPI_BIAS_RESID, float><<<dim3(HID / BN, TOK / BM), 256, HGEMM_SMEM>>>(
        ffb, wt_ff2, b_ff2, x1, out, TOK, HID, FF);
}